// round 16
// baseline (speedup 1.0000x reference)
#include <cuda_runtime.h>
#include <cuda_fp16.h>
#include <math.h>
#include <stdint.h>

// ---------------- problem constants ----------------
namespace {
constexpr int B_    = 32;
constexpr int NSEQ  = 4096;
constexpr int C     = 256;
constexpr int SH    = 32;
constexpr int H_    = 8;
constexpr int ROWS  = B_ * NSEQ;          // 131072
constexpr int BW    = B_ * 64;            // 2048 windows
constexpr int HID   = 1024;
constexpr float SCALE = 0.17677669529663687f;  // 32^-0.5

constexpr size_t OFF_QKVW = 0;                       // 768*256
constexpr size_t OFF_LEPE = 196608;                  // 256*768
constexpr size_t OFF_PROJ = 393216;                  // 256*256
constexpr size_t OFF_FC1  = 458752;                  // 1024*256
constexpr size_t OFF_FC2  = 720896;                  // 256*1024
constexpr size_t WBF_TOT  = 983040;

constexpr int ATILE_B = 256 * 128;              // A tile bytes (256 rows x 128B)
constexpr int BTILE_B = 128 * 128;              // B tile bytes
constexpr int BUF_B   = ATILE_B + BTILE_B;      // 49152 B per stage
constexpr int SMEM_DYN = 2 * BUF_B;             // 98304 B (2-stage)
}

// ---------------- scratch (fp16 activations; fp32 trunk) ----------------
__device__ __half g_hs  [(size_t)ROWS * C];
__device__ __half g_qkv [(size_t)ROWS * 3 * C];
__device__ __half g_attn[(size_t)ROWS * C];
__device__ __half g_lepe[(size_t)ROWS * C];
__device__ float  g_x1  [(size_t)ROWS * C];
__device__ __half g_m1  [(size_t)ROWS * HID];
__device__ __half g_wbf[WBF_TOT];

// ---------------- helpers ----------------
__device__ __forceinline__ uint32_t pack_h2(float a, float b) {
    __half2 p = __floats2half2_rn(a, b);
    return *reinterpret_cast<uint32_t*>(&p);
}
__device__ __forceinline__ void cpa16(uint32_t dst, const void* src) {
    asm volatile("cp.async.cg.shared.global [%0], [%1], 16;" :: "r"(dst), "l"(src));
}
__device__ __forceinline__ void cpa16_pred(uint32_t dst, const void* src, bool v) {
    int sz = v ? 16 : 0;
    asm volatile("cp.async.cg.shared.global [%0], [%1], 16, %2;"
                 :: "r"(dst), "l"(src), "r"(sz));
}
__device__ __forceinline__ void ldmx4(uint32_t& r0, uint32_t& r1, uint32_t& r2, uint32_t& r3,
                                      uint32_t addr) {
    asm volatile("ldmatrix.sync.aligned.m8n8.x4.shared.b16 {%0,%1,%2,%3}, [%4];"
                 : "=r"(r0), "=r"(r1), "=r"(r2), "=r"(r3) : "r"(addr));
}
// fp16-accumulate HMMA
__device__ __forceinline__ void mma16816h(uint32_t* c, const uint32_t* a, const uint32_t* b) {
    asm volatile(
        "mma.sync.aligned.m16n8k16.row.col.f16.f16.f16.f16 "
        "{%0,%1}, {%2,%3,%4,%5}, {%6,%7}, {%0,%1};"
        : "+r"(c[0]), "+r"(c[1])
        : "r"(a[0]), "r"(a[1]), "r"(a[2]), "r"(a[3]), "r"(b[0]), "r"(b[1]));
}

// ---------------- weight conversion ----------------
__global__ void cvt_kernel(const float* __restrict__ src, __half* __restrict__ dst, int n) {
    int i = blockIdx.x * 256 + threadIdx.x;
    if (i < n) dst[i] = __float2half(src[i]);
}
__global__ void posw_kernel(const float* __restrict__ pw, __half* __restrict__ dst) {
    int idx = blockIdx.x * 256 + threadIdx.x;      // 196608
    int o = idx / 768, kk = idx % 768;
    int t = kk >> 8, i = kk & 255;
    dst[idx] = __float2half(pw[(size_t)o * 768 + i * 3 + t]);
}

// ---------------- LayerNorm, 4 rows per block (optional shifted read) -------
__global__ __launch_bounds__(256) void ln_kernel(const float* __restrict__ x,
                                                 const float* __restrict__ w,
                                                 const float* __restrict__ bvec,
                                                 __half* __restrict__ out, int shift) {
    int tid  = threadIdx.x;
    int rloc = tid >> 6;
    int t    = tid & 63;
    int row  = blockIdx.x * 4 + rloc;
    int b = row >> 12, n = row & 4095;
    int src = (b << 12) | ((n + shift) & 4095);
    const float4* xin = reinterpret_cast<const float4*>(x + (size_t)src * C);
    float4 v = xin[t];
    float s = v.x + v.y + v.z + v.w;
    float q = v.x * v.x + v.y * v.y + v.z * v.z + v.w * v.w;
#pragma unroll
    for (int o = 16; o > 0; o >>= 1) {
        s += __shfl_xor_sync(0xffffffffu, s, o);
        q += __shfl_xor_sync(0xffffffffu, q, o);
    }
    __shared__ float shs[4][2], shq[4][2];
    int wir = (t >> 5);
    if ((t & 31) == 0) { shs[rloc][wir] = s; shq[rloc][wir] = q; }
    __syncthreads();
    s = shs[rloc][0] + shs[rloc][1];
    q = shq[rloc][0] + shq[rloc][1];
    float mean = s * (1.0f / C);
    float var  = q * (1.0f / C) - mean * mean;
    float rstd = rsqrtf(var + 1e-5f);
    float4 wv = reinterpret_cast<const float4*>(w)[t];
    float4 bv = reinterpret_cast<const float4*>(bvec)[t];
    uint2 pk = make_uint2(pack_h2((v.x - mean) * rstd * wv.x + bv.x,
                                  (v.y - mean) * rstd * wv.y + bv.y),
                          pack_h2((v.z - mean) * rstd * wv.z + bv.z,
                                  (v.w - mean) * rstd * wv.w + bv.w));
    reinterpret_cast<uint2*>(out + (size_t)row * C)[t] = pk;
}

// ---------------- windowed attention: 128 thr, half2 math ------------------
__global__ __launch_bounds__(128) void attn_kernel(const __half* __restrict__ qkv,
                                                   const float* __restrict__ mask,
                                                   __half* __restrict__ out) {
    int wh = blockIdx.x;
    int bw = wh >> 3;
    int h  = wh & 7;
    int wIdx = bw & 63;
    int t    = threadIdx.x & 63;
    int half = threadIdx.x >> 6;

    __shared__ __half2 ks2[64][17];
    __shared__ __half2 vs2[64][17];
    __shared__ __half2 pacc[64][17];
    __shared__ float psum[64];

    const __half* rowp = qkv + ((size_t)bw * 64 + t) * 768 + h * 32;
    {
        const __half* kv = rowp + (half ? 512 : 256);
        uint32_t* dsh = reinterpret_cast<uint32_t*>(half ? &vs2[t][0] : &ks2[t][0]);
#pragma unroll
        for (int c = 0; c < 4; c++) {
            uint4 q4 = *reinterpret_cast<const uint4*>(kv + c * 8);
            dsh[c * 4 + 0] = q4.x; dsh[c * 4 + 1] = q4.y;
            dsh[c * 4 + 2] = q4.z; dsh[c * 4 + 3] = q4.w;
        }
    }
    __half2 q2[16];
    const __half2 sc2 = __float2half2_rn(SCALE);
#pragma unroll
    for (int c = 0; c < 4; c++) {
        uint4 q4 = *reinterpret_cast<const uint4*>(rowp + c * 8);
        const uint32_t* w32 = &q4.x;
#pragma unroll
        for (int u = 0; u < 4; u++)
            q2[c * 4 + u] = __hmul2(*reinterpret_cast<const __half2*>(&w32[u]), sc2);
    }
    __syncthreads();

    const float* mrow = mask + ((size_t)wIdx * 64 + t) * 64 + half * 32;
    float sum = 0.f;
    __half2 accA[16], accB[16];
    const __half2 z2 = __floats2half2_rn(0.f, 0.f);
#pragma unroll
    for (int d = 0; d < 16; d++) { accA[d] = z2; accB[d] = z2; }
#pragma unroll 2
    for (int j0 = 0; j0 < 32; j0++) {
        int j = half * 32 + j0;
        __half2 d2 = z2;
#pragma unroll
        for (int d = 0; d < 16; d++) d2 = __hfma2(q2[d], ks2[j][d], d2);
        float s = __low2float(d2) + __high2float(d2) + mrow[j0];
        float e = __expf(s);
        sum += e;
        __half2 e2 = __float2half2_rn(e);
        if (j0 & 1) {
#pragma unroll
            for (int d = 0; d < 16; d++) accB[d] = __hfma2(e2, vs2[j][d], accB[d]);
        } else {
#pragma unroll
            for (int d = 0; d < 16; d++) accA[d] = __hfma2(e2, vs2[j][d], accA[d]);
        }
    }
    if (half) {
#pragma unroll
        for (int d = 0; d < 16; d++) pacc[t][d] = __hadd2(accA[d], accB[d]);
        psum[t] = sum;
    }
    __syncthreads();
    if (!half) {
        float inv = 1.f / (sum + psum[t]);
        __half* orow = out + ((size_t)bw * 64 + t) * 256 + h * 32;
#pragma unroll
        for (int u = 0; u < 16; u++) {
            float2 a = __half22float2(__hadd2(accA[u], accB[u]));
            float2 p = __half22float2(pacc[t][u]);
            *reinterpret_cast<uint32_t*>(orow + 2 * u) =
                pack_h2((a.x + p.x) * inv, (a.y + p.y) * inv);
        }
    }
}

// ---------------- 2-stage swizzled fp16 HMMA NT GEMM, 256x128 tile, BK=64 ---
// warp grid 2(wm) x 4(wn); each warp: 128 M-rows x 32 N-cols (8 m16 x 4 n8)
// MODE 0: QKV | 1: LEPE gather | 2: PROJ (+shift+residual, fp32 out) |
// 3: FC1+GELU | 4: FC2 (+residual, fp32 out)
template <int MODE>
__global__ __launch_bounds__(256, 2) void bgemm_kernel(
    const __half* __restrict__ A, const __half* __restrict__ W,
    const float* __restrict__ bias, void* __restrict__ CoutV,
    const float* __restrict__ extra, const __half* __restrict__ A2, int Kin) {
    extern __shared__ __half smem[];
    const int tid  = threadIdx.x;
    const int lane = tid & 31;
    const int warp = tid >> 5;
    const int wm   = warp >> 2;      // 0..1  -> M offset wm*128
    const int wn   = warp & 3;       // 0..3  -> N offset wn*32
    const int m0 = blockIdx.y * 256;
    const int n0 = blockIdx.x * 128;

    const uint32_t sbase = (uint32_t)__cvta_generic_to_shared(smem);
    const int nslab = Kin >> 6;

    auto load_slab = [&](int s) {
        const int p = s & 1;
        const int k0 = s << 6;
        uint32_t a_s = sbase + p * BUF_B;
        uint32_t b_s = a_s + ATILE_B;
        // A: 2048 chunks of 16B (256 rows x 8 chunks)
#pragma unroll
        for (int i = 0; i < 8; i++) {
            int ch = tid + i * 256;
            int row = ch >> 3;                 // 0..255
            int c16 = ch & 7;
            int colh = c16 * 8;
            uint32_t doff = row * 128 + ((c16 ^ (row & 7)) << 4);
            if (MODE == 1) {
                int d = (k0 >> 8) - 1;
                int R = m0 + row;
                bool v = ((unsigned)((R & 63) + d) < 64u);
                const __half* src =
                    v ? (A + (size_t)(R + d) * 768 + ((k0 + colh) & 255)) : A;
                cpa16_pred(a_s + doff, src, v);
            } else if (MODE == 2) {
                size_t o = (size_t)(m0 + row) * Kin + k0 + colh;
                uint4 a4 = *reinterpret_cast<const uint4*>(A + o);
                uint4 l4 = *reinterpret_cast<const uint4*>(A2 + o);
                uint32_t* xa = &a4.x;
                const uint32_t* xl = &l4.x;
#pragma unroll
                for (int u = 0; u < 4; u++) {
                    __half2 s2 = __hadd2(*reinterpret_cast<__half2*>(&xa[u]),
                                         *reinterpret_cast<const __half2*>(&xl[u]));
                    xa[u] = *reinterpret_cast<uint32_t*>(&s2);
                }
                *reinterpret_cast<uint4*>(
                    reinterpret_cast<char*>(smem) + p * BUF_B + doff) = a4;
            } else {
                cpa16(a_s + doff, A + (size_t)(m0 + row) * Kin + k0 + colh);
            }
        }
        // B: 1024 chunks
#pragma unroll
        for (int i = 0; i < 4; i++) {
            int ch = tid + i * 256;
            int row = ch >> 3;                 // 0..127
            int c16 = ch & 7;
            int colh = c16 * 8;
            uint32_t doff = row * 128 + ((c16 ^ (row & 7)) << 4);
            cpa16(b_s + doff, W + (size_t)(n0 + row) * Kin + k0 + colh);
        }
        asm volatile("cp.async.commit_group;" ::: "memory");
    };

    uint32_t c[8][4][2];
#pragma unroll
    for (int i = 0; i < 8; i++)
#pragma unroll
        for (int j = 0; j < 4; j++) { c[i][j][0] = 0u; c[i][j][1] = 0u; }

    load_slab(0);
    for (int s = 0; s < nslab; s++) {
        if (s + 1 < nslab) {
            load_slab(s + 1);
            asm volatile("cp.async.wait_group 1;" ::: "memory");
        } else {
            asm volatile("cp.async.wait_group 0;" ::: "memory");
        }
        __syncthreads();

        const int p = s & 1;
        uint32_t a_s = sbase + p * BUF_B;
        uint32_t b_s = a_s + ATILE_B;
#pragma unroll
        for (int ks = 0; ks < 4; ks++) {
            uint32_t b[4][2];
            const int c16b = ks * 2 + ((lane >> 3) & 1);
#pragma unroll
            for (int jj = 0; jj < 2; jj++) {
                int row = wn * 32 + jj * 16 + (lane & 7) + ((lane >> 4) << 3);
                ldmx4(b[2 * jj][0], b[2 * jj][1], b[2 * jj + 1][0], b[2 * jj + 1][1],
                      b_s + row * 128 + ((c16b ^ (row & 7)) << 4));
            }
            const int c16a = ks * 2 + (lane >> 4);
#pragma unroll
            for (int i = 0; i < 8; i++) {
                uint32_t a[4];
                int row = wm * 128 + i * 16 + (lane & 15);
                ldmx4(a[0], a[1], a[2], a[3],
                      a_s + row * 128 + ((c16a ^ (row & 7)) << 4));
#pragma unroll
                for (int j = 0; j < 4; j++) mma16816h(c[i][j], a, b[j]);
            }
        }
        __syncthreads();
    }

    // epilogue
#pragma unroll
    for (int i = 0; i < 8; i++) {
        int r_base = m0 + wm * 128 + i * 16 + (lane >> 2);
#pragma unroll
        for (int j = 0; j < 4; j++) {
            int col = n0 + wn * 32 + j * 8 + (lane & 3) * 2;
            float2 bv = *reinterpret_cast<const float2*>(bias + col);
#pragma unroll
            for (int hh = 0; hh < 2; hh++) {
                int r = r_base + hh * 8;
                float2 cv = __half22float2(*reinterpret_cast<__half2*>(&c[i][j][hh]));
                float v0 = cv.x + bv.x;
                float v1 = cv.y + bv.y;
                if (MODE == 0) {
                    __half* Cb = (__half*)CoutV;
                    *reinterpret_cast<uint32_t*>(Cb + (size_t)r * 768 + col) = pack_h2(v0, v1);
                } else if (MODE == 1) {
                    __half* Cb = (__half*)CoutV;
                    *reinterpret_cast<uint32_t*>(Cb + (size_t)r * 256 + col) = pack_h2(v0, v1);
                } else if (MODE == 2) {
                    float* Cf = (float*)CoutV;
                    int b = r >> 12, n = r & 4095;
                    int n2 = (n + SH) & 4095;
                    size_t o = ((size_t)((b << 12) | n2)) * 256 + col;
                    float2 e = *reinterpret_cast<const float2*>(extra + o);
                    *reinterpret_cast<float2*>(Cf + o) = make_float2(e.x + v0, e.y + v1);
                } else if (MODE == 3) {
                    __half* Cb = (__half*)CoutV;
                    float g0 = 0.5f * v0 * (1.f + erff(v0 * 0.70710678118654752f));
                    float g1 = 0.5f * v1 * (1.f + erff(v1 * 0.70710678118654752f));
                    *reinterpret_cast<uint32_t*>(Cb + (size_t)r * 1024 + col) = pack_h2(g0, g1);
                } else {
                    float* Cf = (float*)CoutV;
                    size_t o = (size_t)r * 256 + col;
                    float2 e = *reinterpret_cast<const float2*>(extra + o);
                    *reinterpret_cast<float2*>(Cf + o) = make_float2(v0 + e.x, v1 + e.y);
                }
            }
        }
    }
}

// ---------------- launch ----------------
extern "C" void kernel_launch(void* const* d_in, const int* in_sizes, int n_in,
                              void* d_out, int out_size) {
    const float* x     = (const float*)d_in[0];
    const float* mask  = (const float*)d_in[1];
    const float* n1w   = (const float*)d_in[2];
    const float* n1b   = (const float*)d_in[3];
    const float* qkvw  = (const float*)d_in[4];
    const float* qkvb  = (const float*)d_in[5];
    const float* posw  = (const float*)d_in[6];
    const float* posb  = (const float*)d_in[7];
    const float* projw = (const float*)d_in[8];
    const float* projb = (const float*)d_in[9];
    const float* n2w   = (const float*)d_in[10];
    const float* n2b   = (const float*)d_in[11];
    const float* fc1w  = (const float*)d_in[12];
    const float* fc1b  = (const float*)d_in[13];
    const float* fc2w  = (const float*)d_in[14];
    const float* fc2b  = (const float*)d_in[15];
    float* out = (float*)d_out;

    __half *hs, *qkv, *attn, *lepe, *m1, *wbf;
    float *x1;
    cudaGetSymbolAddress((void**)&hs,   g_hs);
    cudaGetSymbolAddress((void**)&qkv,  g_qkv);
    cudaGetSymbolAddress((void**)&attn, g_attn);
    cudaGetSymbolAddress((void**)&lepe, g_lepe);
    cudaGetSymbolAddress((void**)&x1,   g_x1);
    cudaGetSymbolAddress((void**)&m1,   g_m1);
    cudaGetSymbolAddress((void**)&wbf,  g_wbf);

    static cudaStream_t s_side = nullptr;
    static cudaEvent_t evStart = nullptr, evA = nullptr, evB = nullptr, evC = nullptr;
    static bool attr_done = false;
    if (!attr_done) {
        auto setup = [](const void* f) {
            cudaFuncSetAttribute(f, cudaFuncAttributeMaxDynamicSharedMemorySize, SMEM_DYN);
            cudaFuncSetAttribute(f, cudaFuncAttributePreferredSharedMemoryCarveout, 100);
        };
        setup((const void*)bgemm_kernel<0>);
        setup((const void*)bgemm_kernel<1>);
        setup((const void*)bgemm_kernel<2>);
        setup((const void*)bgemm_kernel<3>);
        setup((const void*)bgemm_kernel<4>);
        cudaStreamCreateWithFlags(&s_side, cudaStreamNonBlocking);
        cudaEventCreateWithFlags(&evStart, cudaEventDisableTiming);
        cudaEventCreateWithFlags(&evA, cudaEventDisableTiming);
        cudaEventCreateWithFlags(&evB, cudaEventDisableTiming);
        cudaEventCreateWithFlags(&evC, cudaEventDisableTiming);
        attr_done = true;
    }

    // fork side stream FROM the capture-origin stream before using it
    cudaEventRecord(evStart, 0);
    cudaStreamWaitEvent(s_side, evStart, 0);

    // weight conversions on side stream, overlapped with LN1 on main
    cvt_kernel<<<768, 256, 0, s_side>>>(qkvw,  wbf + OFF_QKVW, 196608);
    posw_kernel<<<768, 256, 0, s_side>>>(posw, wbf + OFF_LEPE);
    cvt_kernel<<<256, 256, 0, s_side>>>(projw, wbf + OFF_PROJ, 65536);
    cvt_kernel<<<1024, 256, 0, s_side>>>(fc1w, wbf + OFF_FC1, 262144);
    cvt_kernel<<<1024, 256, 0, s_side>>>(fc2w, wbf + OFF_FC2, 262144);
    cudaEventRecord(evC, s_side);

    ln_kernel<<<ROWS / 4, 256>>>(x, n1w, n1b, hs, SH);
    cudaStreamWaitEvent(0, evC, 0);
    bgemm_kernel<0><<<dim3(6, ROWS / 256), 256, SMEM_DYN>>>(
        hs, wbf + OFF_QKVW, qkvb, qkv, nullptr, nullptr, 256);

    // fork: attention on side stream, LePE GEMM on main stream (independent)
    cudaEventRecord(evA, 0);
    cudaStreamWaitEvent(s_side, evA, 0);
    attn_kernel<<<BW * H_, 128, 0, s_side>>>(qkv, mask, attn);
    cudaEventRecord(evB, s_side);

    // LEPE: Kout = 256 -> grid.x = 2  (R15 bug: was 1, left half of lepe unwritten)
    bgemm_kernel<1><<<dim3(2, ROWS / 256), 256, SMEM_DYN>>>(
        qkv + 512, wbf + OFF_LEPE, posb, lepe, nullptr, nullptr, 768);

    // join: proj needs both attn and lepe
    cudaStreamWaitEvent(0, evB, 0);
    bgemm_kernel<2><<<dim3(2, ROWS / 256), 256, SMEM_DYN>>>(
        attn, wbf + OFF_PROJ, projb, x1, x, lepe, 256);

    ln_kernel<<<ROWS / 4, 256>>>(x1, n2w, n2b, hs, 0);
    bgemm_kernel<3><<<dim3(8, ROWS / 256), 256, SMEM_DYN>>>(
        hs, wbf + OFF_FC1, fc1b, m1, nullptr, nullptr, 256);
    bgemm_kernel<4><<<dim3(2, ROWS / 256), 256, SMEM_DYN>>>(
        m1, wbf + OFF_FC2, fc2b, out, x1, nullptr, 1024);
}

// round 17
// speedup vs baseline: 1.0364x; 1.0364x over previous
#include <cuda_runtime.h>
#include <cuda_fp16.h>
#include <math.h>
#include <stdint.h>

// ---------------- problem constants ----------------
namespace {
constexpr int B_    = 32;
constexpr int NSEQ  = 4096;
constexpr int C     = 256;
constexpr int SH    = 32;
constexpr int H_    = 8;
constexpr int ROWS  = B_ * NSEQ;          // 131072
constexpr int BW    = B_ * 64;            // 2048 windows
constexpr int HID   = 1024;
constexpr float SCALE = 0.17677669529663687f;  // 32^-0.5

constexpr size_t OFF_QKVW = 0;                       // 768*256
constexpr size_t OFF_LEPE = 196608;                  // 256*768
constexpr size_t OFF_PROJ = 393216;                  // 256*256
constexpr size_t OFF_FC1  = 458752;                  // 1024*256
constexpr size_t OFF_FC2  = 720896;                  // 256*1024
constexpr size_t WBF_TOT  = 983040;

constexpr int TILE_B  = 128 * 128;              // bytes per tile (swizzled 128B rows)
constexpr int BUF_B   = 2 * TILE_B;             // A+B per stage = 32768 B
constexpr int SMEM_DYN = 2 * BUF_B;             // 65536 B (2-stage -> 3 CTAs/SM)
}

// ---------------- scratch (fp16 activations; fp32 trunk) ----------------
__device__ __half g_hs  [(size_t)ROWS * C];
__device__ __half g_qkv [(size_t)ROWS * 3 * C];
__device__ __half g_attn[(size_t)ROWS * C];
__device__ __half g_lepe[(size_t)ROWS * C];
__device__ float  g_x1  [(size_t)ROWS * C];
__device__ __half g_m1  [(size_t)ROWS * HID];
__device__ __half g_wbf[WBF_TOT];

// ---------------- helpers ----------------
__device__ __forceinline__ uint32_t pack_h2(float a, float b) {
    __half2 p = __floats2half2_rn(a, b);
    return *reinterpret_cast<uint32_t*>(&p);
}
__device__ __forceinline__ void cpa16(uint32_t dst, const void* src) {
    asm volatile("cp.async.cg.shared.global [%0], [%1], 16;" :: "r"(dst), "l"(src));
}
__device__ __forceinline__ void cpa16_pred(uint32_t dst, const void* src, bool v) {
    int sz = v ? 16 : 0;
    asm volatile("cp.async.cg.shared.global [%0], [%1], 16, %2;"
                 :: "r"(dst), "l"(src), "r"(sz));
}
__device__ __forceinline__ void ldmx4(uint32_t& r0, uint32_t& r1, uint32_t& r2, uint32_t& r3,
                                      uint32_t addr) {
    asm volatile("ldmatrix.sync.aligned.m8n8.x4.shared.b16 {%0,%1,%2,%3}, [%4];"
                 : "=r"(r0), "=r"(r1), "=r"(r2), "=r"(r3) : "r"(addr));
}
// fp16-accumulate HMMA
__device__ __forceinline__ void mma16816h(uint32_t* c, const uint32_t* a, const uint32_t* b) {
    asm volatile(
        "mma.sync.aligned.m16n8k16.row.col.f16.f16.f16.f16 "
        "{%0,%1}, {%2,%3,%4,%5}, {%6,%7}, {%0,%1};"
        : "+r"(c[0]), "+r"(c[1])
        : "r"(a[0]), "r"(a[1]), "r"(a[2]), "r"(a[3]), "r"(b[0]), "r"(b[1]));
}

// ---------------- weight conversion ----------------
__global__ void cvt_kernel(const float* __restrict__ src, __half* __restrict__ dst, int n) {
    int i = blockIdx.x * 256 + threadIdx.x;
    if (i < n) dst[i] = __float2half(src[i]);
}
__global__ void posw_kernel(const float* __restrict__ pw, __half* __restrict__ dst) {
    int idx = blockIdx.x * 256 + threadIdx.x;      // 196608
    int o = idx / 768, kk = idx % 768;
    int t = kk >> 8, i = kk & 255;
    dst[idx] = __float2half(pw[(size_t)o * 768 + i * 3 + t]);
}

// ---------------- LayerNorm, 4 rows per block (optional shifted read) -------
__global__ __launch_bounds__(256) void ln_kernel(const float* __restrict__ x,
                                                 const float* __restrict__ w,
                                                 const float* __restrict__ bvec,
                                                 __half* __restrict__ out, int shift) {
    int tid  = threadIdx.x;
    int rloc = tid >> 6;
    int t    = tid & 63;
    int row  = blockIdx.x * 4 + rloc;
    int b = row >> 12, n = row & 4095;
    int src = (b << 12) | ((n + shift) & 4095);
    const float4* xin = reinterpret_cast<const float4*>(x + (size_t)src * C);
    float4 v = xin[t];
    float s = v.x + v.y + v.z + v.w;
    float q = v.x * v.x + v.y * v.y + v.z * v.z + v.w * v.w;
#pragma unroll
    for (int o = 16; o > 0; o >>= 1) {
        s += __shfl_xor_sync(0xffffffffu, s, o);
        q += __shfl_xor_sync(0xffffffffu, q, o);
    }
    __shared__ float shs[4][2], shq[4][2];
    int wir = (t >> 5);
    if ((t & 31) == 0) { shs[rloc][wir] = s; shq[rloc][wir] = q; }
    __syncthreads();
    s = shs[rloc][0] + shs[rloc][1];
    q = shq[rloc][0] + shq[rloc][1];
    float mean = s * (1.0f / C);
    float var  = q * (1.0f / C) - mean * mean;
    float rstd = rsqrtf(var + 1e-5f);
    float4 wv = reinterpret_cast<const float4*>(w)[t];
    float4 bv = reinterpret_cast<const float4*>(bvec)[t];
    uint2 pk = make_uint2(pack_h2((v.x - mean) * rstd * wv.x + bv.x,
                                  (v.y - mean) * rstd * wv.y + bv.y),
                          pack_h2((v.z - mean) * rstd * wv.z + bv.z,
                                  (v.w - mean) * rstd * wv.w + bv.w));
    reinterpret_cast<uint2*>(out + (size_t)row * C)[t] = pk;
}

// ---------------- windowed attention: 128 thr, half2 math ------------------
__global__ __launch_bounds__(128) void attn_kernel(const __half* __restrict__ qkv,
                                                   const float* __restrict__ mask,
                                                   __half* __restrict__ out) {
    int wh = blockIdx.x;
    int bw = wh >> 3;
    int h  = wh & 7;
    int wIdx = bw & 63;
    int t    = threadIdx.x & 63;
    int half = threadIdx.x >> 6;

    __shared__ __half2 ks2[64][17];
    __shared__ __half2 vs2[64][17];
    __shared__ __half2 pacc[64][17];
    __shared__ float psum[64];

    const __half* rowp = qkv + ((size_t)bw * 64 + t) * 768 + h * 32;
    {
        const __half* kv = rowp + (half ? 512 : 256);
        uint32_t* dsh = reinterpret_cast<uint32_t*>(half ? &vs2[t][0] : &ks2[t][0]);
#pragma unroll
        for (int c = 0; c < 4; c++) {
            uint4 q4 = *reinterpret_cast<const uint4*>(kv + c * 8);
            dsh[c * 4 + 0] = q4.x; dsh[c * 4 + 1] = q4.y;
            dsh[c * 4 + 2] = q4.z; dsh[c * 4 + 3] = q4.w;
        }
    }
    __half2 q2[16];
    const __half2 sc2 = __float2half2_rn(SCALE);
#pragma unroll
    for (int c = 0; c < 4; c++) {
        uint4 q4 = *reinterpret_cast<const uint4*>(rowp + c * 8);
        const uint32_t* w32 = &q4.x;
#pragma unroll
        for (int u = 0; u < 4; u++)
            q2[c * 4 + u] = __hmul2(*reinterpret_cast<const __half2*>(&w32[u]), sc2);
    }
    __syncthreads();

    const float* mrow = mask + ((size_t)wIdx * 64 + t) * 64 + half * 32;
    float sum = 0.f;
    __half2 accA[16], accB[16];
    const __half2 z2 = __floats2half2_rn(0.f, 0.f);
#pragma unroll
    for (int d = 0; d < 16; d++) { accA[d] = z2; accB[d] = z2; }
#pragma unroll 2
    for (int j0 = 0; j0 < 32; j0++) {
        int j = half * 32 + j0;
        __half2 d2 = z2;
#pragma unroll
        for (int d = 0; d < 16; d++) d2 = __hfma2(q2[d], ks2[j][d], d2);
        float s = __low2float(d2) + __high2float(d2) + mrow[j0];
        float e = __expf(s);
        sum += e;
        __half2 e2 = __float2half2_rn(e);
        if (j0 & 1) {
#pragma unroll
            for (int d = 0; d < 16; d++) accB[d] = __hfma2(e2, vs2[j][d], accB[d]);
        } else {
#pragma unroll
            for (int d = 0; d < 16; d++) accA[d] = __hfma2(e2, vs2[j][d], accA[d]);
        }
    }
    if (half) {
#pragma unroll
        for (int d = 0; d < 16; d++) pacc[t][d] = __hadd2(accA[d], accB[d]);
        psum[t] = sum;
    }
    __syncthreads();
    if (!half) {
        float inv = 1.f / (sum + psum[t]);
        __half* orow = out + ((size_t)bw * 64 + t) * 256 + h * 32;
#pragma unroll
        for (int u = 0; u < 16; u++) {
            float2 a = __half22float2(__hadd2(accA[u], accB[u]));
            float2 p = __half22float2(pacc[t][u]);
            *reinterpret_cast<uint32_t*>(orow + 2 * u) =
                pack_h2((a.x + p.x) * inv, (a.y + p.y) * inv);
        }
    }
}

// ---------------- 2-stage swizzled fp16 HMMA NT GEMM, 128x128, BK=64 --------
// 3 CTAs/SM target (64KB smem/CTA, <=85 regs)
// MODE 0: QKV | 1: LEPE gather | 2: PROJ (+shift+residual, fp32 out) |
// 3: FC1+GELU | 4: FC2 (+residual, fp32 out)
template <int MODE>
__global__ __launch_bounds__(256, 3) void bgemm_kernel(
    const __half* __restrict__ A, const __half* __restrict__ W,
    const float* __restrict__ bias, void* __restrict__ CoutV,
    const float* __restrict__ extra, const __half* __restrict__ A2, int Kin) {
    extern __shared__ __half smem[];
    const int tid  = threadIdx.x;
    const int lane = tid & 31;
    const int warp = tid >> 5;
    const int wm   = warp >> 2;
    const int wn   = warp & 3;
    const int m0 = blockIdx.y * 128;
    const int n0 = blockIdx.x * 128;

    const uint32_t sbase = (uint32_t)__cvta_generic_to_shared(smem);
    const int nslab = Kin >> 6;

    auto load_slab = [&](int s) {
        const int p = s & 1;
        const int k0 = s << 6;
        uint32_t a_s = sbase + p * BUF_B;
        uint32_t b_s = a_s + TILE_B;
#pragma unroll
        for (int i = 0; i < 4; i++) {
            int ch = tid + i * 256;            // 0..1023
            int row = ch >> 3;                 // 0..127
            int c16 = ch & 7;
            int colh = c16 * 8;
            uint32_t doff = row * 128 + ((c16 ^ (row & 7)) << 4);
            if (MODE == 1) {
                int d = (k0 >> 8) - 1;
                int R = m0 + row;
                bool v = ((unsigned)((R & 63) + d) < 64u);
                const __half* src =
                    v ? (A + (size_t)(R + d) * 768 + ((k0 + colh) & 255)) : A;
                cpa16_pred(a_s + doff, src, v);
            } else if (MODE == 2) {
                size_t o = (size_t)(m0 + row) * Kin + k0 + colh;
                uint4 a4 = *reinterpret_cast<const uint4*>(A + o);
                uint4 l4 = *reinterpret_cast<const uint4*>(A2 + o);
                uint32_t* xa = &a4.x;
                const uint32_t* xl = &l4.x;
#pragma unroll
                for (int u = 0; u < 4; u++) {
                    __half2 s2 = __hadd2(*reinterpret_cast<__half2*>(&xa[u]),
                                         *reinterpret_cast<const __half2*>(&xl[u]));
                    xa[u] = *reinterpret_cast<uint32_t*>(&s2);
                }
                *reinterpret_cast<uint4*>(
                    reinterpret_cast<char*>(smem) + p * BUF_B + doff) = a4;
            } else {
                cpa16(a_s + doff, A + (size_t)(m0 + row) * Kin + k0 + colh);
            }
            cpa16(b_s + doff, W + (size_t)(n0 + row) * Kin + k0 + colh);
        }
        asm volatile("cp.async.commit_group;" ::: "memory");
    };

    uint32_t c[4][4][2];
#pragma unroll
    for (int i = 0; i < 4; i++)
#pragma unroll
        for (int j = 0; j < 4; j++) { c[i][j][0] = 0u; c[i][j][1] = 0u; }

    load_slab(0);
    for (int s = 0; s < nslab; s++) {
        if (s + 1 < nslab) {
            load_slab(s + 1);
            asm volatile("cp.async.wait_group 1;" ::: "memory");
        } else {
            asm volatile("cp.async.wait_group 0;" ::: "memory");
        }
        __syncthreads();

        const int p = s & 1;
        uint32_t a_s = sbase + p * BUF_B;
        uint32_t b_s = a_s + TILE_B;
#pragma unroll
        for (int ks = 0; ks < 4; ks++) {
            uint32_t a[4][4], b[4][2];
            const int c16a = ks * 2 + (lane >> 4);
#pragma unroll
            for (int i = 0; i < 4; i++) {
                int row = wm * 64 + i * 16 + (lane & 15);
                ldmx4(a[i][0], a[i][1], a[i][2], a[i][3],
                      a_s + row * 128 + ((c16a ^ (row & 7)) << 4));
            }
            const int c16b = ks * 2 + ((lane >> 3) & 1);
#pragma unroll
            for (int jj = 0; jj < 2; jj++) {
                int row = wn * 32 + jj * 16 + (lane & 7) + ((lane >> 4) << 3);
                ldmx4(b[2 * jj][0], b[2 * jj][1], b[2 * jj + 1][0], b[2 * jj + 1][1],
                      b_s + row * 128 + ((c16b ^ (row & 7)) << 4));
            }
#pragma unroll
            for (int i = 0; i < 4; i++)
#pragma unroll
                for (int j = 0; j < 4; j++) mma16816h(c[i][j], a[i], b[j]);
        }
        __syncthreads();
    }

    // epilogue
#pragma unroll
    for (int i = 0; i < 4; i++) {
        int r_base = m0 + wm * 64 + i * 16 + (lane >> 2);
#pragma unroll
        for (int j = 0; j < 4; j++) {
            int col = n0 + wn * 32 + j * 8 + (lane & 3) * 2;
            float2 bv = *reinterpret_cast<const float2*>(bias + col);
#pragma unroll
            for (int hh = 0; hh < 2; hh++) {
                int r = r_base + hh * 8;
                float2 cv = __half22float2(*reinterpret_cast<__half2*>(&c[i][j][hh]));
                float v0 = cv.x + bv.x;
                float v1 = cv.y + bv.y;
                if (MODE == 0) {
                    __half* Cb = (__half*)CoutV;
                    *reinterpret_cast<uint32_t*>(Cb + (size_t)r * 768 + col) = pack_h2(v0, v1);
                } else if (MODE == 1) {
                    __half* Cb = (__half*)CoutV;
                    *reinterpret_cast<uint32_t*>(Cb + (size_t)r * 256 + col) = pack_h2(v0, v1);
                } else if (MODE == 2) {
                    float* Cf = (float*)CoutV;
                    int b = r >> 12, n = r & 4095;
                    int n2 = (n + SH) & 4095;
                    size_t o = ((size_t)((b << 12) | n2)) * 256 + col;
                    float2 e = *reinterpret_cast<const float2*>(extra + o);
                    *reinterpret_cast<float2*>(Cf + o) = make_float2(e.x + v0, e.y + v1);
                } else if (MODE == 3) {
                    __half* Cb = (__half*)CoutV;
                    float g0 = 0.5f * v0 * (1.f + erff(v0 * 0.70710678118654752f));
                    float g1 = 0.5f * v1 * (1.f + erff(v1 * 0.70710678118654752f));
                    *reinterpret_cast<uint32_t*>(Cb + (size_t)r * 1024 + col) = pack_h2(g0, g1);
                } else {
                    float* Cf = (float*)CoutV;
                    size_t o = (size_t)r * 256 + col;
                    float2 e = *reinterpret_cast<const float2*>(extra + o);
                    *reinterpret_cast<float2*>(Cf + o) = make_float2(v0 + e.x, v1 + e.y);
                }
            }
        }
    }
}

// ---------------- launch ----------------
extern "C" void kernel_launch(void* const* d_in, const int* in_sizes, int n_in,
                              void* d_out, int out_size) {
    const float* x     = (const float*)d_in[0];
    const float* mask  = (const float*)d_in[1];
    const float* n1w   = (const float*)d_in[2];
    const float* n1b   = (const float*)d_in[3];
    const float* qkvw  = (const float*)d_in[4];
    const float* qkvb  = (const float*)d_in[5];
    const float* posw  = (const float*)d_in[6];
    const float* posb  = (const float*)d_in[7];
    const float* projw = (const float*)d_in[8];
    const float* projb = (const float*)d_in[9];
    const float* n2w   = (const float*)d_in[10];
    const float* n2b   = (const float*)d_in[11];
    const float* fc1w  = (const float*)d_in[12];
    const float* fc1b  = (const float*)d_in[13];
    const float* fc2w  = (const float*)d_in[14];
    const float* fc2b  = (const float*)d_in[15];
    float* out = (float*)d_out;

    __half *hs, *qkv, *attn, *lepe, *m1, *wbf;
    float *x1;
    cudaGetSymbolAddress((void**)&hs,   g_hs);
    cudaGetSymbolAddress((void**)&qkv,  g_qkv);
    cudaGetSymbolAddress((void**)&attn, g_attn);
    cudaGetSymbolAddress((void**)&lepe, g_lepe);
    cudaGetSymbolAddress((void**)&x1,   g_x1);
    cudaGetSymbolAddress((void**)&m1,   g_m1);
    cudaGetSymbolAddress((void**)&wbf,  g_wbf);

    static cudaStream_t s_side = nullptr;
    static cudaEvent_t evStart = nullptr, evA = nullptr, evB = nullptr, evC = nullptr;
    static bool attr_done = false;
    if (!attr_done) {
        auto setup = [](const void* f) {
            cudaFuncSetAttribute(f, cudaFuncAttributeMaxDynamicSharedMemorySize, SMEM_DYN);
            cudaFuncSetAttribute(f, cudaFuncAttributePreferredSharedMemoryCarveout, 100);
        };
        setup((const void*)bgemm_kernel<0>);
        setup((const void*)bgemm_kernel<1>);
        setup((const void*)bgemm_kernel<2>);
        setup((const void*)bgemm_kernel<3>);
        setup((const void*)bgemm_kernel<4>);
        cudaStreamCreateWithFlags(&s_side, cudaStreamNonBlocking);
        cudaEventCreateWithFlags(&evStart, cudaEventDisableTiming);
        cudaEventCreateWithFlags(&evA, cudaEventDisableTiming);
        cudaEventCreateWithFlags(&evB, cudaEventDisableTiming);
        cudaEventCreateWithFlags(&evC, cudaEventDisableTiming);
        attr_done = true;
    }

    // fork side stream FROM the capture-origin stream before using it
    cudaEventRecord(evStart, 0);
    cudaStreamWaitEvent(s_side, evStart, 0);

    // weight conversions on side stream, overlapped with LN1 on main
    cvt_kernel<<<768, 256, 0, s_side>>>(qkvw,  wbf + OFF_QKVW, 196608);
    posw_kernel<<<768, 256, 0, s_side>>>(posw, wbf + OFF_LEPE);
    cvt_kernel<<<256, 256, 0, s_side>>>(projw, wbf + OFF_PROJ, 65536);
    cvt_kernel<<<1024, 256, 0, s_side>>>(fc1w, wbf + OFF_FC1, 262144);
    cvt_kernel<<<1024, 256, 0, s_side>>>(fc2w, wbf + OFF_FC2, 262144);
    cudaEventRecord(evC, s_side);

    ln_kernel<<<ROWS / 4, 256>>>(x, n1w, n1b, hs, SH);
    cudaStreamWaitEvent(0, evC, 0);
    bgemm_kernel<0><<<dim3(6, ROWS / 128), 256, SMEM_DYN>>>(
        hs, wbf + OFF_QKVW, qkvb, qkv, nullptr, nullptr, 256);

    // fork: attention on side stream, LePE GEMM on main stream (independent)
    cudaEventRecord(evA, 0);
    cudaStreamWaitEvent(s_side, evA, 0);
    attn_kernel<<<BW * H_, 128, 0, s_side>>>(qkv, mask, attn);
    cudaEventRecord(evB, s_side);

    bgemm_kernel<1><<<dim3(2, ROWS / 128), 256, SMEM_DYN>>>(
        qkv + 512, wbf + OFF_LEPE, posb, lepe, nullptr, nullptr, 768);

    // join: proj needs both attn and lepe
    cudaStreamWaitEvent(0, evB, 0);
    bgemm_kernel<2><<<dim3(2, ROWS / 128), 256, SMEM_DYN>>>(
        attn, wbf + OFF_PROJ, projb, x1, x, lepe, 256);

    ln_kernel<<<ROWS / 4, 256>>>(x1, n2w, n2b, hs, 0);
    bgemm_kernel<3><<<dim3(8, ROWS / 128), 256, SMEM_DYN>>>(
        hs, wbf + OFF_FC1, fc1b, m1, nullptr, nullptr, 256);
    bgemm_kernel<4><<<dim3(2, ROWS / 128), 256, SMEM_DYN>>>(
        m1, wbf + OFF_FC2, fc2b, out, x1, nullptr, 1024);
}